// round 1
// baseline (speedup 1.0000x reference)
#include <cuda_runtime.h>
#include <math.h>

#define S_LEN 4096
#define D_MODEL 1024

// Scratch (allocation-free rule: __device__ globals)
__device__ float g_Q[S_LEN * D_MODEL];
__device__ float g_K[S_LEN * D_MODEL];
__device__ float g_V[S_LEN * D_MODEL];
__device__ float g_Pscratch[S_LEN * S_LEN];  // fallback if out_size too small

// ---------------------------------------------------------------------------
// NT GEMM: C[M,N] = alpha * A[M,K] @ B[N,K]^T   (both A,B row-major, K contig)
// BM=BN=64, BK=16, 256 threads, 4x4 micro-tile per thread.
// ---------------------------------------------------------------------------
__global__ void gemm_nt_kernel(const float* __restrict__ A,
                               const float* __restrict__ B,
                               float* __restrict__ C,
                               int M, int N, int K, float alpha)
{
    const int BM = 64, BN = 64, BK = 16;
    __shared__ float As[16][64];
    __shared__ float Bs[16][64];

    const int tid = threadIdx.x;        // 0..255
    const int tx  = tid & 15;           // 0..15  -> n micro
    const int ty  = tid >> 4;           // 0..15  -> m micro
    const int m0  = blockIdx.y * BM;
    const int n0  = blockIdx.x * BN;

    const int lrow = tid >> 2;          // 0..63
    const int lcol = (tid & 3) * 4;     // 0,4,8,12

    float acc[4][4];
    #pragma unroll
    for (int i = 0; i < 4; i++)
        #pragma unroll
        for (int j = 0; j < 4; j++) acc[i][j] = 0.f;

    for (int k0 = 0; k0 < K; k0 += BK) {
        // A tile: rows m0..m0+63, cols k0..k0+15 ; store transposed As[k][m]
        {
            float4 v = *reinterpret_cast<const float4*>(
                &A[(size_t)(m0 + lrow) * K + k0 + lcol]);
            As[lcol + 0][lrow] = v.x;
            As[lcol + 1][lrow] = v.y;
            As[lcol + 2][lrow] = v.z;
            As[lcol + 3][lrow] = v.w;
        }
        // B tile: rows n0..n0+63, cols k0..k0+15 ; store transposed Bs[k][n]
        {
            float4 v = *reinterpret_cast<const float4*>(
                &B[(size_t)(n0 + lrow) * K + k0 + lcol]);
            Bs[lcol + 0][lrow] = v.x;
            Bs[lcol + 1][lrow] = v.y;
            Bs[lcol + 2][lrow] = v.z;
            Bs[lcol + 3][lrow] = v.w;
        }
        __syncthreads();

        #pragma unroll
        for (int kk = 0; kk < BK; kk++) {
            float a[4], b[4];
            *reinterpret_cast<float4*>(a) =
                *reinterpret_cast<const float4*>(&As[kk][ty * 4]);
            *reinterpret_cast<float4*>(b) =
                *reinterpret_cast<const float4*>(&Bs[kk][tx * 4]);
            #pragma unroll
            for (int i = 0; i < 4; i++)
                #pragma unroll
                for (int j = 0; j < 4; j++)
                    acc[i][j] = fmaf(a[i], b[j], acc[i][j]);
        }
        __syncthreads();
    }

    #pragma unroll
    for (int i = 0; i < 4; i++) {
        float4 r;
        r.x = alpha * acc[i][0];
        r.y = alpha * acc[i][1];
        r.z = alpha * acc[i][2];
        r.w = alpha * acc[i][3];
        *reinterpret_cast<float4*>(
            &C[(size_t)(m0 + ty * 4 + i) * N + n0 + tx * 4]) = r;
    }
}

// ---------------------------------------------------------------------------
// NN GEMM: C[M,N] = A[M,K] @ B[K,N]   (A row-major K-contig, B row-major N-contig)
// ---------------------------------------------------------------------------
__global__ void gemm_nn_kernel(const float* __restrict__ A,
                               const float* __restrict__ B,
                               float* __restrict__ C,
                               int M, int N, int K)
{
    const int BM = 64, BN = 64, BK = 16;
    __shared__ float As[16][64];
    __shared__ float Bs[16][64];

    const int tid = threadIdx.x;
    const int tx  = tid & 15;
    const int ty  = tid >> 4;
    const int m0  = blockIdx.y * BM;
    const int n0  = blockIdx.x * BN;

    float acc[4][4];
    #pragma unroll
    for (int i = 0; i < 4; i++)
        #pragma unroll
        for (int j = 0; j < 4; j++) acc[i][j] = 0.f;

    const int arow = tid >> 2;          // 0..63
    const int acol = (tid & 3) * 4;     // 0,4,8,12
    const int brow = tid >> 4;          // 0..15
    const int bcol = (tid & 15) * 4;    // 0..60

    for (int k0 = 0; k0 < K; k0 += BK) {
        {
            float4 v = *reinterpret_cast<const float4*>(
                &A[(size_t)(m0 + arow) * K + k0 + acol]);
            As[acol + 0][arow] = v.x;
            As[acol + 1][arow] = v.y;
            As[acol + 2][arow] = v.z;
            As[acol + 3][arow] = v.w;
        }
        {
            float4 v = *reinterpret_cast<const float4*>(
                &B[(size_t)(k0 + brow) * N + n0 + bcol]);
            *reinterpret_cast<float4*>(&Bs[brow][bcol]) = v;
        }
        __syncthreads();

        #pragma unroll
        for (int kk = 0; kk < BK; kk++) {
            float a[4], b[4];
            *reinterpret_cast<float4*>(a) =
                *reinterpret_cast<const float4*>(&As[kk][ty * 4]);
            *reinterpret_cast<float4*>(b) =
                *reinterpret_cast<const float4*>(&Bs[kk][tx * 4]);
            #pragma unroll
            for (int i = 0; i < 4; i++)
                #pragma unroll
                for (int j = 0; j < 4; j++)
                    acc[i][j] = fmaf(a[i], b[j], acc[i][j]);
        }
        __syncthreads();
    }

    #pragma unroll
    for (int i = 0; i < 4; i++) {
        float4 r;
        r.x = acc[i][0]; r.y = acc[i][1]; r.z = acc[i][2]; r.w = acc[i][3];
        *reinterpret_cast<float4*>(
            &C[(size_t)(m0 + ty * 4 + i) * N + n0 + tx * 4]) = r;
    }
}

// ---------------------------------------------------------------------------
// Row softmax in place: one block per row of length n.
// ---------------------------------------------------------------------------
__global__ void softmax_rows_kernel(float* __restrict__ P, int n)
{
    float* p = P + (size_t)blockIdx.x * n;
    __shared__ float red[256];
    const int t = threadIdx.x;

    float m = -INFINITY;
    for (int i = t; i < n; i += 256) m = fmaxf(m, p[i]);
    red[t] = m;
    __syncthreads();
    for (int s = 128; s > 0; s >>= 1) {
        if (t < s) red[t] = fmaxf(red[t], red[t + s]);
        __syncthreads();
    }
    m = red[0];
    __syncthreads();

    float sum = 0.f;
    for (int i = t; i < n; i += 256) {
        float e = expf(p[i] - m);
        p[i] = e;
        sum += e;
    }
    red[t] = sum;
    __syncthreads();
    for (int s = 128; s > 0; s >>= 1) {
        if (t < s) red[t] += red[t + s];
        __syncthreads();
    }
    float inv = 1.f / red[0];
    __syncthreads();

    for (int i = t; i < n; i += 256) p[i] *= inv;
}

// ---------------------------------------------------------------------------
extern "C" void kernel_launch(void* const* d_in, const int* in_sizes, int n_in,
                              void* d_out, int out_size)
{
    const float* x  = (const float*)d_in[0];
    const float* Wq = (const float*)d_in[1];
    const float* Wk = (const float*)d_in[2];
    const float* Wv = (const float*)d_in[3];
    float* out = (float*)d_out;

    float* dQ; cudaGetSymbolAddress((void**)&dQ, g_Q);
    float* dK; cudaGetSymbolAddress((void**)&dK, g_K);
    float* dV; cudaGetSymbolAddress((void**)&dV, g_V);
    float* dPs; cudaGetSymbolAddress((void**)&dPs, g_Pscratch);

    float* Vs = out;  // [S, D] first in tuple order
    const long long need = (long long)S_LEN * D_MODEL + (long long)S_LEN * S_LEN;
    float* P = (out_size >= need) ? (out + (size_t)S_LEN * D_MODEL) : dPs;

    const float scale = 1.0f / 32.0f;  // 1/sqrt(1024)

    dim3 blk(256);
    // QKV projections: [4096,1024] x [1024,1024]^T
    dim3 gproj(D_MODEL / 64, S_LEN / 64);
    gemm_nt_kernel<<<gproj, blk>>>(x, Wq, dQ, S_LEN, D_MODEL, D_MODEL, 1.0f);
    gemm_nt_kernel<<<gproj, blk>>>(x, Wk, dK, S_LEN, D_MODEL, D_MODEL, 1.0f);
    gemm_nt_kernel<<<gproj, blk>>>(x, Wv, dV, S_LEN, D_MODEL, D_MODEL, 1.0f);

    // scores = Q @ K^T * scale  -> P
    dim3 gsc(S_LEN / 64, S_LEN / 64);
    gemm_nt_kernel<<<gsc, blk>>>(dQ, dK, P, S_LEN, S_LEN, D_MODEL, scale);

    // softmax rows in place
    softmax_rows_kernel<<<S_LEN, 256>>>(P, S_LEN);

    // Vs = P @ V
    dim3 gpv(D_MODEL / 64, S_LEN / 64);
    gemm_nn_kernel<<<gpv, blk>>>(P, dV, Vs, S_LEN, D_MODEL, S_LEN);
}

// round 3
// speedup vs baseline: 2.9729x; 2.9729x over previous
#include <cuda_runtime.h>
#include <cuda_bf16.h>
#include <math.h>
#include <cstdint>

#define S_LEN 4096
#define D_MODEL 1024

// ============================ PTX helpers (sm_80-class only) ===============
__device__ __forceinline__ uint32_t smem_u32(const void* p) {
    uint32_t a;
    asm("{ .reg .u64 t; cvta.to.shared.u64 t, %1; cvt.u32.u64 %0, t; }"
        : "=r"(a) : "l"(p));
    return a;
}

__device__ __forceinline__ void cp_async16(uint32_t smem_addr, const void* gptr) {
    asm volatile("cp.async.cg.shared.global [%0], [%1], 16;"
                 :: "r"(smem_addr), "l"(gptr));
}
#define CP_COMMIT() asm volatile("cp.async.commit_group;" ::: "memory")
template<int N> __device__ __forceinline__ void cp_wait() {
    asm volatile("cp.async.wait_group %0;" :: "n"(N) : "memory");
}

__device__ __forceinline__ void ldmatrix_x4(uint32_t* r, uint32_t addr) {
    asm volatile("ldmatrix.sync.aligned.m8n8.x4.shared.b16 {%0,%1,%2,%3}, [%4];"
        : "=r"(r[0]), "=r"(r[1]), "=r"(r[2]), "=r"(r[3]) : "r"(addr));
}
__device__ __forceinline__ void ldmatrix_x2(uint32_t* r, uint32_t addr) {
    asm volatile("ldmatrix.sync.aligned.m8n8.x2.shared.b16 {%0,%1}, [%2];"
        : "=r"(r[0]), "=r"(r[1]) : "r"(addr));
}
__device__ __forceinline__ void mma_bf16(float* d, const uint32_t* a,
                                         const uint32_t* b) {
    asm volatile(
      "mma.sync.aligned.m16n8k16.row.col.f32.bf16.bf16.f32 "
      "{%0,%1,%2,%3}, {%4,%5,%6,%7}, {%8,%9}, {%0,%1,%2,%3};"
      : "+f"(d[0]), "+f"(d[1]), "+f"(d[2]), "+f"(d[3])
      : "r"(a[0]), "r"(a[1]), "r"(a[2]), "r"(a[3]), "r"(b[0]), "r"(b[1]));
}

// ============================ scratch (no allocs) ==========================
__device__ __nv_bfloat16 g_x_hi[S_LEN * D_MODEL],  g_x_lo[S_LEN * D_MODEL];
__device__ __nv_bfloat16 g_Wq_hi[D_MODEL * D_MODEL], g_Wq_lo[D_MODEL * D_MODEL];
__device__ __nv_bfloat16 g_Wk_hi[D_MODEL * D_MODEL], g_Wk_lo[D_MODEL * D_MODEL];
__device__ __nv_bfloat16 g_Wv_hi[D_MODEL * D_MODEL], g_Wv_lo[D_MODEL * D_MODEL];
__device__ __nv_bfloat16 g_Q_hi[S_LEN * D_MODEL],  g_Q_lo[S_LEN * D_MODEL];
__device__ __nv_bfloat16 g_K_hi[S_LEN * D_MODEL],  g_K_lo[S_LEN * D_MODEL];
__device__ __nv_bfloat16 g_VT_hi[D_MODEL * S_LEN], g_VT_lo[D_MODEL * S_LEN];
__device__ __nv_bfloat16 g_P_hi[(size_t)S_LEN * S_LEN];
__device__ __nv_bfloat16 g_P_lo[(size_t)S_LEN * S_LEN];
__device__ float g_Pscratch[(size_t)S_LEN * S_LEN];  // fallback

// ============================ split kernel =================================
__global__ void split_bf16_kernel(const float* __restrict__ src,
                                  __nv_bfloat16* __restrict__ hi,
                                  __nv_bfloat16* __restrict__ lo, int n)
{
    int i = blockIdx.x * blockDim.x + threadIdx.x;
    if (i < n) {
        float v = src[i];
        __nv_bfloat16 h = __float2bfloat16(v);
        hi[i] = h;
        lo[i] = __float2bfloat16(v - __bfloat162float(h));
    }
}

// ============================ mma.sync GEMM ================================
// C[M,N] = A[M,K] @ B[N,K]^T, bf16x3 split, fp32 accum.
// If Cf: fp32 out. Else bf16 hi/lo out.
#define BM 128
#define BN 128
#define BK 32
#define LDS 40                      // bf16 elems per smem row (80B, conflict-free)
#define TILE_ELEMS (BM * LDS)       // 5120
#define STAGE_ELEMS (4 * TILE_ELEMS)
#define GEMM_SMEM_BYTES (2 * STAGE_ELEMS * 2)  // 81920

__device__ __forceinline__ void load_tile(
    const __nv_bfloat16* __restrict__ g, int row0, int K, int k0,
    uint32_t sm_base_bytes, int tid)
{
    #pragma unroll
    for (int j = 0; j < 2; j++) {
        int v = tid + j * 256;          // 0..511 16B vectors
        int r = v >> 2;                 // 0..127
        int c = (v & 3) * 8;            // 0,8,16,24 (elems)
        const void* gp = g + (size_t)(row0 + r) * K + k0 + c;
        cp_async16(sm_base_bytes + (uint32_t)(r * LDS + c) * 2, gp);
    }
}

__global__ void __launch_bounds__(256)
gemm_bf16x3_mma(const __nv_bfloat16* __restrict__ A_hi,
                const __nv_bfloat16* __restrict__ A_lo,
                const __nv_bfloat16* __restrict__ B_hi,
                const __nv_bfloat16* __restrict__ B_lo,
                float* __restrict__ Cf,
                __nv_bfloat16* __restrict__ C_hi,
                __nv_bfloat16* __restrict__ C_lo,
                int M, int N, int K)
{
    extern __shared__ __nv_bfloat16 smem[];
    const int tid = threadIdx.x;
    const int wid = tid >> 5;
    const int lane = tid & 31;
    const int m0 = blockIdx.y * BM;
    const int n0 = blockIdx.x * BN;
    const int wm = wid >> 2;            // 0..1
    const int wn = wid & 3;             // 0..3

    const uint32_t sb = smem_u32(smem);
    // stage s, tile t (0=Ah,1=Al,2=Bh,3=Bl) byte base:
    auto tile_base = [&](int s, int t) -> uint32_t {
        return sb + (uint32_t)((s * STAGE_ELEMS + t * TILE_ELEMS) * 2);
    };

    float acc[4][4][4];
    #pragma unroll
    for (int a = 0; a < 4; a++)
        #pragma unroll
        for (int b = 0; b < 4; b++)
            #pragma unroll
            for (int c = 0; c < 4; c++) acc[a][b][c] = 0.f;

    const int nch = K / BK;

    // prologue: stage 0 and 1
    load_tile(A_hi, m0, K, 0, tile_base(0, 0), tid);
    load_tile(A_lo, m0, K, 0, tile_base(0, 1), tid);
    load_tile(B_hi, n0, K, 0, tile_base(0, 2), tid);
    load_tile(B_lo, n0, K, 0, tile_base(0, 3), tid);
    CP_COMMIT();
    if (nch > 1) {
        load_tile(A_hi, m0, K, BK, tile_base(1, 0), tid);
        load_tile(A_lo, m0, K, BK, tile_base(1, 1), tid);
        load_tile(B_hi, n0, K, BK, tile_base(1, 2), tid);
        load_tile(B_lo, n0, K, BK, tile_base(1, 3), tid);
        CP_COMMIT();
    }
    cp_wait<1>();
    __syncthreads();

    // ldmatrix per-lane address components (element units)
    const int a_r = wm * 64 + (lane & 15);
    const int a_c8 = (lane >> 4) * 8;
    const int b_r = wn * 32 + (lane & 7);
    const int b_c8 = ((lane >> 3) & 1) * 8;

    for (int i = 0; i < nch; i++) {
        const int s = i & 1;
        const uint32_t aAh = tile_base(s, 0);
        const uint32_t aAl = tile_base(s, 1);
        const uint32_t aBh = tile_base(s, 2);
        const uint32_t aBl = tile_base(s, 3);

        #pragma unroll
        for (int ks = 0; ks < 2; ks++) {
            uint32_t ah[4][4], al[4][4], bh[4][2], bl[4][2];
            const int acol = ks * 16 + a_c8;
            const int bcol = ks * 16 + b_c8;
            #pragma unroll
            for (int mt = 0; mt < 4; mt++) {
                uint32_t off = (uint32_t)(((a_r + mt * 16) * LDS + acol) * 2);
                ldmatrix_x4(ah[mt], aAh + off);
                ldmatrix_x4(al[mt], aAl + off);
            }
            #pragma unroll
            for (int nt = 0; nt < 4; nt++) {
                uint32_t off = (uint32_t)(((b_r + nt * 8) * LDS + bcol) * 2);
                ldmatrix_x2(bh[nt], aBh + off);
                ldmatrix_x2(bl[nt], aBl + off);
            }
            #pragma unroll
            for (int mt = 0; mt < 4; mt++)
                #pragma unroll
                for (int nt = 0; nt < 4; nt++) {
                    mma_bf16(acc[mt][nt], ah[mt], bh[nt]);
                    mma_bf16(acc[mt][nt], ah[mt], bl[nt]);
                    mma_bf16(acc[mt][nt], al[mt], bh[nt]);
                }
        }
        __syncthreads();

        if (i + 2 < nch) {
            const int k0 = (i + 2) * BK;
            load_tile(A_hi, m0, K, k0, tile_base(s, 0), tid);
            load_tile(A_lo, m0, K, k0, tile_base(s, 1), tid);
            load_tile(B_hi, n0, K, k0, tile_base(s, 2), tid);
            load_tile(B_lo, n0, K, k0, tile_base(s, 3), tid);
            CP_COMMIT();
            cp_wait<1>();
        } else {
            cp_wait<0>();
        }
        __syncthreads();
    }

    // epilogue
    const int tr = lane >> 2;           // 0..7
    const int tc = (lane & 3) * 2;      // 0,2,4,6
    const int r0 = m0 + wm * 64;
    const int c0 = n0 + wn * 32;

    #pragma unroll
    for (int mt = 0; mt < 4; mt++) {
        #pragma unroll
        for (int nt = 0; nt < 4; nt++) {
            const float* d = acc[mt][nt];
            const int row = r0 + mt * 16 + tr;
            const int col = c0 + nt * 8 + tc;
            if (Cf != nullptr) {
                float2 v0 = make_float2(d[0], d[1]);
                float2 v1 = make_float2(d[2], d[3]);
                *reinterpret_cast<float2*>(&Cf[(size_t)row * N + col]) = v0;
                *reinterpret_cast<float2*>(&Cf[(size_t)(row + 8) * N + col]) = v1;
            } else {
                #pragma unroll
                for (int e = 0; e < 2; e++) {
                    const int rr = row + e * 8;
                    __nv_bfloat162 h2, l2;
                    {
                        float v = d[e * 2 + 0];
                        __nv_bfloat16 h = __float2bfloat16(v);
                        h2.x = h; l2.x = __float2bfloat16(v - __bfloat162float(h));
                    }
                    {
                        float v = d[e * 2 + 1];
                        __nv_bfloat16 h = __float2bfloat16(v);
                        h2.y = h; l2.y = __float2bfloat16(v - __bfloat162float(h));
                    }
                    *reinterpret_cast<__nv_bfloat162*>(
                        &C_hi[(size_t)rr * N + col]) = h2;
                    *reinterpret_cast<__nv_bfloat162*>(
                        &C_lo[(size_t)rr * N + col]) = l2;
                }
            }
        }
    }
}

// ============================ softmax ======================================
// In place on raw scores: apply *1/32, softmax per row, write fp32 + bf16 split.
__global__ void softmax_rows_kernel(float* __restrict__ P,
                                    __nv_bfloat16* __restrict__ Phi,
                                    __nv_bfloat16* __restrict__ Plo, int n)
{
    float* p = P + (size_t)blockIdx.x * n;
    __nv_bfloat16* ph = Phi + (size_t)blockIdx.x * n;
    __nv_bfloat16* pl = Plo + (size_t)blockIdx.x * n;
    __shared__ float red[256];
    const int t = threadIdx.x;
    const float scale = 1.0f / 32.0f;

    float m = -INFINITY;
    for (int i = t; i < n; i += 256) m = fmaxf(m, p[i] * scale);
    red[t] = m;
    __syncthreads();
    for (int s = 128; s > 0; s >>= 1) {
        if (t < s) red[t] = fmaxf(red[t], red[t + s]);
        __syncthreads();
    }
    m = red[0];
    __syncthreads();

    float sum = 0.f;
    for (int i = t; i < n; i += 256) {
        float e = expf(p[i] * scale - m);
        p[i] = e;
        sum += e;
    }
    red[t] = sum;
    __syncthreads();
    for (int s = 128; s > 0; s >>= 1) {
        if (t < s) red[t] += red[t + s];
        __syncthreads();
    }
    float inv = 1.f / red[0];
    __syncthreads();

    for (int i = t; i < n; i += 256) {
        float v = p[i] * inv;
        p[i] = v;
        __nv_bfloat16 h = __float2bfloat16(v);
        ph[i] = h;
        pl[i] = __float2bfloat16(v - __bfloat162float(h));
    }
}

// ============================ launch =======================================
extern "C" void kernel_launch(void* const* d_in, const int* in_sizes, int n_in,
                              void* d_out, int out_size)
{
    const float* x  = (const float*)d_in[0];
    const float* Wq = (const float*)d_in[1];
    const float* Wk = (const float*)d_in[2];
    const float* Wv = (const float*)d_in[3];
    float* out = (float*)d_out;

    __nv_bfloat16 *xh, *xl, *wqh, *wql, *wkh, *wkl, *wvh, *wvl;
    __nv_bfloat16 *qh, *ql, *kh, *kl, *vth, *vtl, *pph, *ppl;
    float* dPs;
    cudaGetSymbolAddress((void**)&xh,  g_x_hi);  cudaGetSymbolAddress((void**)&xl,  g_x_lo);
    cudaGetSymbolAddress((void**)&wqh, g_Wq_hi); cudaGetSymbolAddress((void**)&wql, g_Wq_lo);
    cudaGetSymbolAddress((void**)&wkh, g_Wk_hi); cudaGetSymbolAddress((void**)&wkl, g_Wk_lo);
    cudaGetSymbolAddress((void**)&wvh, g_Wv_hi); cudaGetSymbolAddress((void**)&wvl, g_Wv_lo);
    cudaGetSymbolAddress((void**)&qh,  g_Q_hi);  cudaGetSymbolAddress((void**)&ql,  g_Q_lo);
    cudaGetSymbolAddress((void**)&kh,  g_K_hi);  cudaGetSymbolAddress((void**)&kl,  g_K_lo);
    cudaGetSymbolAddress((void**)&vth, g_VT_hi); cudaGetSymbolAddress((void**)&vtl, g_VT_lo);
    cudaGetSymbolAddress((void**)&pph, g_P_hi);  cudaGetSymbolAddress((void**)&ppl, g_P_lo);
    cudaGetSymbolAddress((void**)&dPs, g_Pscratch);

    float* Vs = out;
    const long long need = (long long)S_LEN * D_MODEL + (long long)S_LEN * S_LEN;
    float* P = (out_size >= need) ? (out + (size_t)S_LEN * D_MODEL) : dPs;

    static bool attr_set = false;
    cudaFuncSetAttribute(gemm_bf16x3_mma,
                         cudaFuncAttributeMaxDynamicSharedMemorySize,
                         GEMM_SMEM_BYTES);
    (void)attr_set;

    // split inputs into bf16 hi/lo
    {
        int n = S_LEN * D_MODEL;
        split_bf16_kernel<<<(n + 255) / 256, 256>>>(x, xh, xl, n);
        int nw = D_MODEL * D_MODEL;
        split_bf16_kernel<<<(nw + 255) / 256, 256>>>(Wq, wqh, wql, nw);
        split_bf16_kernel<<<(nw + 255) / 256, 256>>>(Wk, wkh, wkl, nw);
        split_bf16_kernel<<<(nw + 255) / 256, 256>>>(Wv, wvh, wvl, nw);
    }

    dim3 blk(256);
    // Q = x @ Wq^T -> bf16 hi/lo  [S, D]
    gemm_bf16x3_mma<<<dim3(D_MODEL / BN, S_LEN / BM), blk, GEMM_SMEM_BYTES>>>(
        xh, xl, wqh, wql, nullptr, qh, ql, S_LEN, D_MODEL, D_MODEL);
    // K = x @ Wk^T -> bf16 hi/lo  [S, D]
    gemm_bf16x3_mma<<<dim3(D_MODEL / BN, S_LEN / BM), blk, GEMM_SMEM_BYTES>>>(
        xh, xl, wkh, wkl, nullptr, kh, kl, S_LEN, D_MODEL, D_MODEL);
    // V^T = Wv @ x^T -> bf16 hi/lo [D, S]  (NT: A=Wv [D,D], B=x [S,D])
    gemm_bf16x3_mma<<<dim3(S_LEN / BN, D_MODEL / BM), blk, GEMM_SMEM_BYTES>>>(
        wvh, wvl, xh, xl, nullptr, vth, vtl, D_MODEL, S_LEN, D_MODEL);
    // scores = Q @ K^T -> fp32 P  [S, S]
    gemm_bf16x3_mma<<<dim3(S_LEN / BN, S_LEN / BM), blk, GEMM_SMEM_BYTES>>>(
        qh, ql, kh, kl, P, nullptr, nullptr, S_LEN, S_LEN, D_MODEL);
    // softmax rows (applies 1/32), emits fp32 P + bf16 hi/lo
    softmax_rows_kernel<<<S_LEN, 256>>>(P, pph, ppl, S_LEN);
    // Vs = P @ (V^T)^T -> fp32  [S, D]  (NT: A=P [S,S], B=VT [D,S])
    gemm_bf16x3_mma<<<dim3(D_MODEL / BN, S_LEN / BM), blk, GEMM_SMEM_BYTES>>>(
        pph, ppl, vth, vtl, Vs, nullptr, nullptr, S_LEN, D_MODEL, S_LEN);
}